// round 3
// baseline (speedup 1.0000x reference)
#include <cuda_runtime.h>

#define B_WIN 4096
#define N_TOK 49
#define C_DIM 512
#define H_NUM 16
#define HD    32
#define NW    64
#define QKV_N 1536
#define M_ROWS (B_WIN * N_TOK)   // 200704

// Scratch (allocation-free rule: __device__ globals)
__device__ float g_qkv[308281344];   // [B_, N, 1536]  = 1.233 GB
__device__ float g_att[102760448];   // [B_, N, 512]   = 411 MB
__device__ float g_bias[H_NUM * N_TOK * N_TOK];  // [H, 49, 49]

// ---------------------------------------------------------------------------
// Precompute relative position bias: g_bias[h][i][j] = table[rpi[i*49+j]][h]
// ---------------------------------------------------------------------------
__global__ void bias_kernel(const float* __restrict__ table,
                            const int* __restrict__ rpi) {
    int idx = blockIdx.x * blockDim.x + threadIdx.x;
    if (idx < H_NUM * N_TOK * N_TOK) {
        int h = idx / (N_TOK * N_TOK);
        int e = idx % (N_TOK * N_TOK);
        g_bias[idx] = table[rpi[e] * H_NUM + h];
    }
}

// ---------------------------------------------------------------------------
// SGEMM: C[M,N] = A[M,K] @ B[K,N] + bias[N]
// 128x128 tile, BK=8, 256 threads, 8x8 per-thread micro-tile (split 4+4).
// Requires M%128==0, N%128==0, K%8==0 (true for both GEMMs here).
// ---------------------------------------------------------------------------
__global__ __launch_bounds__(256) void sgemm_bias(
    const float* __restrict__ A, const float* __restrict__ B,
    const float* __restrict__ bias, float* __restrict__ C,
    int M, int N, int K)
{
    __shared__ float As[8][128];
    __shared__ float Bs[8][128];

    const int tid = threadIdx.x;
    const int tx = tid & 15;         // 0..15 (col group)
    const int ty = tid >> 4;         // 0..15 (row group)

    const float* Ab = A + (size_t)blockIdx.y * 128 * K;
    const float* Bb = B + blockIdx.x * 128;

    // A tile load: 128 rows x 8 cols = 256 float4 (one per thread)
    const int aRow = tid >> 1;
    const int aCol = (tid & 1) * 4;
    // B tile load: 8 rows x 128 cols = 256 float4
    const int bRow = tid >> 5;
    const int bCol = (tid & 31) * 4;

    float acc[8][8];
    #pragma unroll
    for (int i = 0; i < 8; i++)
        #pragma unroll
        for (int j = 0; j < 8; j++) acc[i][j] = 0.f;

    for (int kt = 0; kt < K; kt += 8) {
        float4 av = *(const float4*)(Ab + (size_t)aRow * K + kt + aCol);
        float4 bv = *(const float4*)(Bb + (size_t)(kt + bRow) * N + bCol);
        __syncthreads();
        As[aCol + 0][aRow] = av.x;
        As[aCol + 1][aRow] = av.y;
        As[aCol + 2][aRow] = av.z;
        As[aCol + 3][aRow] = av.w;
        *(float4*)&Bs[bRow][bCol] = bv;
        __syncthreads();

        #pragma unroll
        for (int kk = 0; kk < 8; kk++) {
            float a[8], b[8];
            *(float4*)(a)     = *(const float4*)&As[kk][ty * 4];
            *(float4*)(a + 4) = *(const float4*)&As[kk][64 + ty * 4];
            *(float4*)(b)     = *(const float4*)&Bs[kk][tx * 4];
            *(float4*)(b + 4) = *(const float4*)&Bs[kk][64 + tx * 4];
            #pragma unroll
            for (int i = 0; i < 8; i++)
                #pragma unroll
                for (int j = 0; j < 8; j++)
                    acc[i][j] = fmaf(a[i], b[j], acc[i][j]);
        }
    }

    // Epilogue: add bias, write float4s
    const int cBase = blockIdx.x * 128;
    float4 bia0 = *(const float4*)(bias + cBase + tx * 4);
    float4 bia1 = *(const float4*)(bias + cBase + 64 + tx * 4);
    const float bv0[4] = {bia0.x, bia0.y, bia0.z, bia0.w};
    const float bv1[4] = {bia1.x, bia1.y, bia1.z, bia1.w};

    #pragma unroll
    for (int ig = 0; ig < 2; ig++) {
        #pragma unroll
        for (int i = 0; i < 4; i++) {
            size_t row = (size_t)blockIdx.y * 128 + ig * 64 + ty * 4 + i;
            float* Crow = C + row * N + cBase;
            float4 o0, o1;
            o0.x = acc[ig * 4 + i][0] + bv0[0];
            o0.y = acc[ig * 4 + i][1] + bv0[1];
            o0.z = acc[ig * 4 + i][2] + bv0[2];
            o0.w = acc[ig * 4 + i][3] + bv0[3];
            o1.x = acc[ig * 4 + i][4] + bv1[0];
            o1.y = acc[ig * 4 + i][5] + bv1[1];
            o1.z = acc[ig * 4 + i][6] + bv1[2];
            o1.w = acc[ig * 4 + i][7] + bv1[3];
            *(float4*)(Crow + tx * 4)      = o0;
            *(float4*)(Crow + 64 + tx * 4) = o1;
        }
    }
}

// ---------------------------------------------------------------------------
// Fused attention: one CTA per (b, h).
// Reads q/k/v slices from g_qkv, computes softmax(q k^T * scale + bias + mask) v
// and writes [B_, N, C]-layout output into g_att (heads interleaved).
// ---------------------------------------------------------------------------
__global__ __launch_bounds__(256) void attn_kernel(const float* __restrict__ mask)
{
    const int h = blockIdx.x;   // 0..15
    const int b = blockIdx.y;   // 0..4095

    __shared__ float s_q[N_TOK * 33];
    __shared__ float s_k[N_TOK * 33];
    __shared__ float s_v[N_TOK * 33];
    __shared__ float s_a[N_TOK * N_TOK];

    const int tid = threadIdx.x;
    const float scale = 0.17677669529663687f;  // 32^-0.5

    const size_t base = (size_t)b * N_TOK * QKV_N + h * HD;
    for (int t = tid; t < N_TOK * HD; t += 256) {
        int n = t >> 5, d = t & 31;
        size_t g = base + (size_t)n * QKV_N + d;
        s_q[n * 33 + d] = g_qkv[g] * scale;
        s_k[n * 33 + d] = g_qkv[g + C_DIM];
        s_v[n * 33 + d] = g_qkv[g + 2 * C_DIM];
    }
    __syncthreads();

    const float* bias_h = g_bias + h * (N_TOK * N_TOK);
    const float* mask_w = mask + (size_t)(b & (NW - 1)) * (N_TOK * N_TOK);

    for (int e = tid; e < N_TOK * N_TOK; e += 256) {
        int r = e / N_TOK, c = e % N_TOK;
        float s = 0.f;
        #pragma unroll
        for (int kk = 0; kk < HD; kk++)
            s = fmaf(s_q[r * 33 + kk], s_k[c * 33 + kk], s);
        s_a[e] = s + bias_h[e] + mask_w[e];
    }
    __syncthreads();

    // Softmax, one warp per row (rows strided by 8 warps)
    const int warp = tid >> 5, lane = tid & 31;
    for (int r = warp; r < N_TOK; r += 8) {
        float x1 = s_a[r * N_TOK + lane];                               // lane < 32 < 49
        float x2 = (lane + 32 < N_TOK) ? s_a[r * N_TOK + lane + 32] : -1e30f;
        float m = fmaxf(x1, x2);
        #pragma unroll
        for (int o = 16; o; o >>= 1) m = fmaxf(m, __shfl_xor_sync(0xffffffffu, m, o));
        float e1 = __expf(x1 - m);
        float e2 = (lane + 32 < N_TOK) ? __expf(x2 - m) : 0.f;
        float s = e1 + e2;
        #pragma unroll
        for (int o = 16; o; o >>= 1) s += __shfl_xor_sync(0xffffffffu, s, o);
        float inv = 1.f / s;
        s_a[r * N_TOK + lane] = e1 * inv;
        if (lane + 32 < N_TOK) s_a[r * N_TOK + lane + 32] = e2 * inv;
    }
    __syncthreads();

    const size_t obase = (size_t)b * N_TOK * C_DIM + h * HD;
    for (int t = tid; t < N_TOK * HD; t += 256) {
        int n = t >> 5, d = t & 31;
        float s = 0.f;
        #pragma unroll
        for (int m = 0; m < N_TOK; m++)
            s = fmaf(s_a[n * N_TOK + m], s_v[m * 33 + d], s);
        g_att[obase + (size_t)n * C_DIM + d] = s;
    }
}

// ---------------------------------------------------------------------------
extern "C" void kernel_launch(void* const* d_in, const int* in_sizes, int n_in,
                              void* d_out, int out_size) {
    const float* x      = (const float*)d_in[0];
    const float* mask   = (const float*)d_in[1];
    const float* qkv_w  = (const float*)d_in[2];
    const float* qkv_b  = (const float*)d_in[3];
    const float* proj_w = (const float*)d_in[4];
    const float* proj_b = (const float*)d_in[5];
    const float* table  = (const float*)d_in[6];
    const int*   rpi    = (const int*)d_in[7];
    float* out = (float*)d_out;

    float* qkv_buf;  cudaGetSymbolAddress((void**)&qkv_buf, g_qkv);
    float* att_buf;  cudaGetSymbolAddress((void**)&att_buf, g_att);

    // 1. relative position bias table expansion
    {
        int total = H_NUM * N_TOK * N_TOK;
        bias_kernel<<<(total + 255) / 256, 256>>>(table, rpi);
    }

    // 2. QKV GEMM: [200704, 512] @ [512, 1536] + qkv_b
    {
        dim3 grid(QKV_N / 128, M_ROWS / 128);
        sgemm_bias<<<grid, 256>>>(x, qkv_w, qkv_b, qkv_buf, M_ROWS, QKV_N, C_DIM);
    }

    // 3. fused window attention -> g_att [B_, N, C]
    {
        dim3 grid(H_NUM, B_WIN);
        attn_kernel<<<grid, 256>>>(mask);
    }

    // 4. proj GEMM: [200704, 512] @ [512, 512] + proj_b -> d_out
    {
        dim3 grid(C_DIM / 128, M_ROWS / 128);
        sgemm_bias<<<grid, 256>>>(att_buf, proj_w, proj_b, out, M_ROWS, C_DIM, C_DIM);
    }
}

// round 5
// speedup vs baseline: 1.7020x; 1.7020x over previous
#include <cuda_runtime.h>
#include <cuda_bf16.h>
#include <cstdint>

#define B_WIN 4096
#define N_TOK 49
#define C_DIM 512
#define H_NUM 16
#define HD    32
#define NW    64
#define QKV_N 1536
#define M_ROWS (B_WIN * N_TOK)   // 200704

// ---------------- scratch (__device__ globals per allocation rules) ----------
__device__ float g_qkv[308281344];                 // [200704, 1536] fp32
__device__ __nv_bfloat16 g_a1hi[102760448];        // x hi       [M, 512] row-major
__device__ __nv_bfloat16 g_a1lo[102760448];        // x lo
__device__ __nv_bfloat16 g_a2hi[102760448];        // attn-out hi [M, 512]
__device__ __nv_bfloat16 g_a2lo[102760448];
__device__ __nv_bfloat16 g_b1hi[786432];           // qkv_w hi [512, 1536] (K,N)
__device__ __nv_bfloat16 g_b1lo[786432];
__device__ __nv_bfloat16 g_b2hi[262144];           // proj_w hi [512, 512]
__device__ __nv_bfloat16 g_b2lo[262144];
__device__ float g_bias[H_NUM * N_TOK * N_TOK];

// ---------------- asm helpers (base-target instructions only) ---------------
__device__ __forceinline__ uint32_t su32(const void* p) {
    return (uint32_t)__cvta_generic_to_shared(p);
}
#define CP16(dst, src) \
    asm volatile("cp.async.cg.shared.global [%0], [%1], 16;" \
                 :: "r"(dst), "l"(src) : "memory")
#define CP_COMMIT() asm volatile("cp.async.commit_group;" ::: "memory")
#define CP_WAIT1()  asm volatile("cp.async.wait_group 1;" ::: "memory")

#define LDSM4(R, addr) \
    asm volatile("ldmatrix.sync.aligned.m8n8.x4.shared.b16 {%0,%1,%2,%3}, [%4];" \
                 : "=r"((R)[0]), "=r"((R)[1]), "=r"((R)[2]), "=r"((R)[3]) \
                 : "r"(addr))
#define LDSM4T(R, addr) \
    asm volatile("ldmatrix.sync.aligned.m8n8.x4.trans.shared.b16 {%0,%1,%2,%3}, [%4];" \
                 : "=r"((R)[0]), "=r"((R)[1]), "=r"((R)[2]), "=r"((R)[3]) \
                 : "r"(addr))
#define MMA16816(D, A, B0, B1) \
    asm volatile("mma.sync.aligned.m16n8k16.row.col.f32.bf16.bf16.f32 " \
                 "{%0,%1,%2,%3}, {%4,%5,%6,%7}, {%8,%9}, {%0,%1,%2,%3};" \
                 : "+f"((D)[0]), "+f"((D)[1]), "+f"((D)[2]), "+f"((D)[3]) \
                 : "r"((A)[0]), "r"((A)[1]), "r"((A)[2]), "r"((A)[3]), \
                   "r"(B0), "r"(B1))

// ---------------------------------------------------------------------------
// bias table expansion
// ---------------------------------------------------------------------------
__global__ void bias_kernel(const float* __restrict__ table,
                            const int* __restrict__ rpi) {
    int idx = blockIdx.x * blockDim.x + threadIdx.x;
    if (idx < H_NUM * N_TOK * N_TOK) {
        int h = idx / (N_TOK * N_TOK);
        int e = idx % (N_TOK * N_TOK);
        g_bias[idx] = table[rpi[e] * H_NUM + h];
    }
}

// ---------------------------------------------------------------------------
// A conversion: [M, 512] fp32 -> row-major hi/lo bf16
// ---------------------------------------------------------------------------
__global__ __launch_bounds__(256) void conv_a_kernel(
    const float* __restrict__ src, __nv_bfloat16* __restrict__ hi,
    __nv_bfloat16* __restrict__ lo) {
    size_t t = (size_t)blockIdx.x * blockDim.x + threadIdx.x;
    size_t base = t * 8;
    if (base >= (size_t)M_ROWS * C_DIM) return;
    float v[8];
    *(float4*)v       = *(const float4*)(src + base);
    *(float4*)(v + 4) = *(const float4*)(src + base + 4);
    union { __nv_bfloat16 h[8]; uint4 u; } hv, lv;
    #pragma unroll
    for (int i = 0; i < 8; i++) {
        hv.h[i] = __float2bfloat16(v[i]);
        lv.h[i] = __float2bfloat16(v[i] - __bfloat162float(hv.h[i]));
    }
    *(uint4*)(hi + base) = hv.u;
    *(uint4*)(lo + base) = lv.u;
}

// ---------------------------------------------------------------------------
// B conversion: W[K,N] fp32 -> same-layout hi/lo bf16 (no transpose)
// ---------------------------------------------------------------------------
__global__ __launch_bounds__(256) void conv_b_kernel(
    const float* __restrict__ w, __nv_bfloat16* __restrict__ hi,
    __nv_bfloat16* __restrict__ lo, int total) {
    size_t t = (size_t)blockIdx.x * blockDim.x + threadIdx.x;
    size_t base = t * 8;
    if (base >= (size_t)total) return;
    float v[8];
    *(float4*)v       = *(const float4*)(w + base);
    *(float4*)(v + 4) = *(const float4*)(w + base + 4);
    union { __nv_bfloat16 h[8]; uint4 u; } hv, lv;
    #pragma unroll
    for (int i = 0; i < 8; i++) {
        hv.h[i] = __float2bfloat16(v[i]);
        lv.h[i] = __float2bfloat16(v[i] - __bfloat162float(hv.h[i]));
    }
    *(uint4*)(hi + base) = hv.u;
    *(uint4*)(lo + base) = lv.u;
}

// ---------------------------------------------------------------------------
// bf16 3-term split GEMM via mma.sync (HMMA).
// C[M,N] = Ahi*Bhi + Ahi*Blo + Alo*Bhi + bias[N], fp32 accumulate.
// A row-major [M,512] bf16, B row-major [512,N] bf16 (K-major rows).
// CTA tile 128x128, BK=32, 256 threads = 8 warps (4 m x 2 n), warp tile 32x64.
// cp.async double-buffered.
//
// smem per stage: Ahi 128x(64B+16 pad)=10240, Alo 10240,
//                 Bhi 32x(256B+16 pad)=8704,  Blo 8704   -> 37888 B
// ---------------------------------------------------------------------------
#define ST_ALO 10240
#define ST_BHI 20480
#define ST_BLO 29184
#define STAGE_SZ 37888
#define GSMEM (2 * STAGE_SZ)

__device__ __forceinline__ void ld_stage(
    uint32_t st, const __nv_bfloat16* Ahi, const __nv_bfloat16* Alo,
    const __nv_bfloat16* Bhi, const __nv_bfloat16* Blo,
    int mbase, int nbase, int kt, int N, int tid) {
    // A tiles: 128 rows x 32 cols bf16 = 512 16B-chunks each
    #pragma unroll
    for (int i = 0; i < 2; i++) {
        int cid = tid + i * 256;
        int row = cid >> 2, cc = cid & 3;
        uint32_t d = st + row * 80 + cc * 16;
        size_t off = (size_t)(mbase + row) * C_DIM + kt * 32 + cc * 8;
        CP16(d,          Ahi + off);
        CP16(d + ST_ALO, Alo + off);
    }
    // B tiles: 32 k-rows x 128 n-cols bf16 = 512 16B-chunks each
    #pragma unroll
    for (int i = 0; i < 2; i++) {
        int cid = tid + i * 256;
        int row = cid >> 4, cc = cid & 15;
        uint32_t d = st + ST_BHI + row * 272 + cc * 16;
        size_t off = (size_t)(kt * 32 + row) * N + nbase + cc * 8;
        CP16(d,                    Bhi + off);
        CP16(d + (ST_BLO - ST_BHI), Blo + off);
    }
}

__global__ __launch_bounds__(256) void mma_gemm(
    const __nv_bfloat16* __restrict__ Ahi, const __nv_bfloat16* __restrict__ Alo,
    const __nv_bfloat16* __restrict__ Bhi, const __nv_bfloat16* __restrict__ Blo,
    const float* __restrict__ bias, float* __restrict__ C, int N) {
    extern __shared__ __align__(1024) char smem[];
    const uint32_t sb = su32(smem);
    const int tid = threadIdx.x;
    const int lane = tid & 31, wid = tid >> 5;
    const int warp_m = wid & 3, warp_n = wid >> 2;
    const int mbase = blockIdx.y * 128, nbase = blockIdx.x * 128;
    const int KT = C_DIM / 32;  // 16

    float acc[2][8][4];
    #pragma unroll
    for (int a = 0; a < 2; a++)
        #pragma unroll
        for (int b = 0; b < 8; b++)
            #pragma unroll
            for (int c = 0; c < 4; c++) acc[a][b][c] = 0.f;

    ld_stage(sb, Ahi, Alo, Bhi, Blo, mbase, nbase, 0, N, tid);
    CP_COMMIT();

    for (int kt = 0; kt < KT; kt++) {
        if (kt + 1 < KT)
            ld_stage(sb + ((kt + 1) & 1) * STAGE_SZ, Ahi, Alo, Bhi, Blo,
                     mbase, nbase, kt + 1, N, tid);
        CP_COMMIT();
        CP_WAIT1();
        __syncthreads();

        const uint32_t st = sb + (kt & 1) * STAGE_SZ;
        #pragma unroll
        for (int ks = 0; ks < 2; ks++) {
            uint32_t ah[2][4], al[2][4];
            #pragma unroll
            for (int mi = 0; mi < 2; mi++) {
                uint32_t addr = st + (warp_m * 32 + mi * 16 + (lane & 15)) * 80
                              + ks * 32 + ((lane >> 4) << 4);
                LDSM4(ah[mi], addr);
                LDSM4(al[mi], addr + ST_ALO);
            }
            #pragma unroll
            for (int nb = 0; nb < 4; nb++) {
                uint32_t bh[4], bl[4];
                uint32_t addr = st + ST_BHI + (ks * 16 + (lane & 15)) * 272
                              + warp_n * 128 + nb * 32 + ((lane & 16) ? 16 : 0);
                LDSM4T(bh, addr);
                LDSM4T(bl, addr + (ST_BLO - ST_BHI));
                #pragma unroll
                for (int mi = 0; mi < 2; mi++) {
                    #pragma unroll
                    for (int s = 0; s < 2; s++) {
                        float* d = acc[mi][nb * 2 + s];
                        MMA16816(d, ah[mi], bh[s * 2], bh[s * 2 + 1]);
                        MMA16816(d, ah[mi], bl[s * 2], bl[s * 2 + 1]);
                        MMA16816(d, al[mi], bh[s * 2], bh[s * 2 + 1]);
                    }
                }
            }
        }
        __syncthreads();
    }

    // epilogue
    const int r0 = lane >> 2, c0 = (lane & 3) * 2;
    #pragma unroll
    for (int mi = 0; mi < 2; mi++) {
        #pragma unroll
        for (int nt = 0; nt < 8; nt++) {
            int row = mbase + warp_m * 32 + mi * 16 + r0;
            int col = nbase + warp_n * 64 + nt * 8 + c0;
            float b0 = bias[col], b1 = bias[col + 1];
            float2 o0 = make_float2(acc[mi][nt][0] + b0, acc[mi][nt][1] + b1);
            float2 o1 = make_float2(acc[mi][nt][2] + b0, acc[mi][nt][3] + b1);
            *(float2*)(C + (size_t)row * N + col)       = o0;
            *(float2*)(C + (size_t)(row + 8) * N + col) = o1;
        }
    }
}

// ---------------------------------------------------------------------------
// Fused attention: one CTA per (b, h). Reads g_qkv fp32 [M,1536], writes
// attention output directly as row-major hi/lo bf16 (GEMM2's A operand).
// ---------------------------------------------------------------------------
__global__ __launch_bounds__(256) void attn_kernel(const float* __restrict__ mask)
{
    const int h = blockIdx.x;   // 0..15
    const int b = blockIdx.y;   // 0..4095

    __shared__ float s_q[N_TOK * 33];
    __shared__ float s_k[N_TOK * 33];
    __shared__ float s_v[N_TOK * 33];
    __shared__ float s_a[N_TOK * N_TOK];

    const int tid = threadIdx.x;
    const float scale = 0.17677669529663687f;  // 32^-0.5

    const size_t base = (size_t)b * N_TOK * QKV_N + h * HD;
    for (int t = tid; t < N_TOK * HD; t += 256) {
        int n = t >> 5, d = t & 31;
        size_t g = base + (size_t)n * QKV_N + d;
        s_q[n * 33 + d] = g_qkv[g] * scale;
        s_k[n * 33 + d] = g_qkv[g + C_DIM];
        s_v[n * 33 + d] = g_qkv[g + 2 * C_DIM];
    }
    __syncthreads();

    const float* bias_h = g_bias + h * (N_TOK * N_TOK);
    const float* mask_w = mask + (size_t)(b & (NW - 1)) * (N_TOK * N_TOK);

    for (int e = tid; e < N_TOK * N_TOK; e += 256) {
        int r = e / N_TOK, c = e % N_TOK;
        float s = 0.f;
        #pragma unroll
        for (int kk = 0; kk < HD; kk++)
            s = fmaf(s_q[r * 33 + kk], s_k[c * 33 + kk], s);
        s_a[e] = s + bias_h[e] + mask_w[e];
    }
    __syncthreads();

    // softmax, one warp per row
    const int warp = tid >> 5, lane = tid & 31;
    for (int r = warp; r < N_TOK; r += 8) {
        float x1 = s_a[r * N_TOK + lane];
        float x2 = (lane + 32 < N_TOK) ? s_a[r * N_TOK + lane + 32] : -1e30f;
        float m = fmaxf(x1, x2);
        #pragma unroll
        for (int o = 16; o; o >>= 1) m = fmaxf(m, __shfl_xor_sync(0xffffffffu, m, o));
        float e1 = __expf(x1 - m);
        float e2 = (lane + 32 < N_TOK) ? __expf(x2 - m) : 0.f;
        float s = e1 + e2;
        #pragma unroll
        for (int o = 16; o; o >>= 1) s += __shfl_xor_sync(0xffffffffu, s, o);
        float inv = 1.f / s;
        s_a[r * N_TOK + lane] = e1 * inv;
        if (lane + 32 < N_TOK) s_a[r * N_TOK + lane + 32] = e2 * inv;
    }
    __syncthreads();

    // out = attn @ v; write row-major hi/lo bf16 for GEMM2.
    if (tid < N_TOK * 4) {
        const int n = tid >> 2, dg = tid & 3;
        float acc[8];
        #pragma unroll
        for (int j = 0; j < 8; j++) acc[j] = 0.f;
        for (int m = 0; m < N_TOK; m++) {
            float a = s_a[n * N_TOK + m];
            const float* vp = s_v + m * 33 + dg * 8;
            #pragma unroll
            for (int j = 0; j < 8; j++) acc[j] = fmaf(a, vp[j], acc[j]);
        }
        union { __nv_bfloat16 hv[8]; uint4 u; } H, L;
        #pragma unroll
        for (int j = 0; j < 8; j++) {
            H.hv[j] = __float2bfloat16(acc[j]);
            L.hv[j] = __float2bfloat16(acc[j] - __bfloat162float(H.hv[j]));
        }
        const int grow = b * N_TOK + n;          // global M row
        const int kcol = h * HD + dg * 8;        // global K col
        size_t off = (size_t)grow * C_DIM + kcol;
        *(uint4*)(g_a2hi + off) = H.u;
        *(uint4*)(g_a2lo + off) = L.u;
    }
}

// ---------------------------------------------------------------------------
extern "C" void kernel_launch(void* const* d_in, const int* in_sizes, int n_in,
                              void* d_out, int out_size) {
    const float* x      = (const float*)d_in[0];
    const float* mask   = (const float*)d_in[1];
    const float* qkv_w  = (const float*)d_in[2];
    const float* qkv_b  = (const float*)d_in[3];
    const float* proj_w = (const float*)d_in[4];
    const float* proj_b = (const float*)d_in[5];
    const float* table  = (const float*)d_in[6];
    const int*   rpi    = (const int*)d_in[7];
    float* out = (float*)d_out;

    float* qkv_buf;           cudaGetSymbolAddress((void**)&qkv_buf, g_qkv);
    __nv_bfloat16 *a1hi, *a1lo, *a2hi, *a2lo, *b1hi, *b1lo, *b2hi, *b2lo;
    cudaGetSymbolAddress((void**)&a1hi, g_a1hi);
    cudaGetSymbolAddress((void**)&a1lo, g_a1lo);
    cudaGetSymbolAddress((void**)&a2hi, g_a2hi);
    cudaGetSymbolAddress((void**)&a2lo, g_a2lo);
    cudaGetSymbolAddress((void**)&b1hi, g_b1hi);
    cudaGetSymbolAddress((void**)&b1lo, g_b1lo);
    cudaGetSymbolAddress((void**)&b2hi, g_b2hi);
    cudaGetSymbolAddress((void**)&b2lo, g_b2lo);

    cudaFuncSetAttribute(mma_gemm, cudaFuncAttributeMaxDynamicSharedMemorySize,
                         GSMEM);

    // 1. bias table expansion
    {
        int total = H_NUM * N_TOK * N_TOK;
        bias_kernel<<<(total + 255) / 256, 256>>>(table, rpi);
    }
    // 2. conversions
    {
        size_t ta = (size_t)M_ROWS * C_DIM / 8;
        conv_a_kernel<<<(unsigned)((ta + 255) / 256), 256>>>(x, a1hi, a1lo);
        int tb1 = C_DIM * QKV_N;
        conv_b_kernel<<<(tb1 / 8 + 255) / 256, 256>>>(qkv_w, b1hi, b1lo, tb1);
        int tb2 = C_DIM * C_DIM;
        conv_b_kernel<<<(tb2 / 8 + 255) / 256, 256>>>(proj_w, b2hi, b2lo, tb2);
    }
    // 3. QKV GEMM: [200704,512] x [512,1536] + qkv_b -> g_qkv (fp32)
    {
        dim3 grid(QKV_N / 128, M_ROWS / 128);
        mma_gemm<<<grid, 256, GSMEM>>>(a1hi, a1lo, b1hi, b1lo, qkv_b,
                                       qkv_buf, QKV_N);
    }
    // 4. fused window attention -> a2 hi/lo bf16
    {
        dim3 grid(H_NUM, B_WIN);
        attn_kernel<<<grid, 256>>>(mask);
    }
    // 5. proj GEMM: [200704,512] x [512,512] + proj_b -> out
    {
        dim3 grid(C_DIM / 128, M_ROWS / 128);
        mma_gemm<<<grid, 256, GSMEM>>>(a2hi, a2lo, b2hi, b2lo, proj_b,
                                       out, C_DIM);
    }
}

// round 7
// speedup vs baseline: 1.7862x; 1.0495x over previous
#include <cuda_runtime.h>
#include <cuda_bf16.h>
#include <cstdint>

#define B_WIN 4096
#define N_TOK 49
#define C_DIM 512
#define H_NUM 16
#define HD    32
#define NW    64
#define QKV_N 1536
#define M_ROWS (B_WIN * N_TOK)   // 200704

// ---------------- scratch (__device__ globals per allocation rules) ----------
__device__ float g_qkv[308281344];                 // [200704, 1536] fp32
__device__ __nv_bfloat16 g_a1hi[102760448];        // x hi       [M, 512] row-major
__device__ __nv_bfloat16 g_a1lo[102760448];        // x lo
__device__ __nv_bfloat16 g_a2hi[102760448];        // attn-out hi [M, 512]
__device__ __nv_bfloat16 g_a2lo[102760448];
__device__ __nv_bfloat16 g_b1hi[786432];           // qkv_w hi [512, 1536] (K,N)
__device__ __nv_bfloat16 g_b1lo[786432];
__device__ __nv_bfloat16 g_b2hi[262144];           // proj_w hi [512, 512]
__device__ __nv_bfloat16 g_b2lo[262144];
__device__ float g_bias[H_NUM * N_TOK * N_TOK];

// ---------------- asm helpers (base-target instructions only) ---------------
__device__ __forceinline__ uint32_t su32(const void* p) {
    return (uint32_t)__cvta_generic_to_shared(p);
}
#define CP16(dst, src) \
    asm volatile("cp.async.cg.shared.global [%0], [%1], 16;" \
                 :: "r"(dst), "l"(src) : "memory")
#define CP_COMMIT() asm volatile("cp.async.commit_group;" ::: "memory")
#define CP_WAIT2()  asm volatile("cp.async.wait_group 2;" ::: "memory")

#define LDSM4(R, addr) \
    asm volatile("ldmatrix.sync.aligned.m8n8.x4.shared.b16 {%0,%1,%2,%3}, [%4];" \
                 : "=r"((R)[0]), "=r"((R)[1]), "=r"((R)[2]), "=r"((R)[3]) \
                 : "r"(addr))
#define LDSM4T(R, addr) \
    asm volatile("ldmatrix.sync.aligned.m8n8.x4.trans.shared.b16 {%0,%1,%2,%3}, [%4];" \
                 : "=r"((R)[0]), "=r"((R)[1]), "=r"((R)[2]), "=r"((R)[3]) \
                 : "r"(addr))
#define MMA16816(D, A, B0, B1) \
    asm volatile("mma.sync.aligned.m16n8k16.row.col.f32.bf16.bf16.f32 " \
                 "{%0,%1,%2,%3}, {%4,%5,%6,%7}, {%8,%9}, {%0,%1,%2,%3};" \
                 : "+f"((D)[0]), "+f"((D)[1]), "+f"((D)[2]), "+f"((D)[3]) \
                 : "r"((A)[0]), "r"((A)[1]), "r"((A)[2]), "r"((A)[3]), \
                   "r"(B0), "r"(B1))

// ---------------------------------------------------------------------------
// bias table expansion
// ---------------------------------------------------------------------------
__global__ void bias_kernel(const float* __restrict__ table,
                            const int* __restrict__ rpi) {
    int idx = blockIdx.x * blockDim.x + threadIdx.x;
    if (idx < H_NUM * N_TOK * N_TOK) {
        int h = idx / (N_TOK * N_TOK);
        int e = idx % (N_TOK * N_TOK);
        g_bias[idx] = table[rpi[e] * H_NUM + h];
    }
}

// ---------------------------------------------------------------------------
// fp32 -> row-major hi/lo bf16 (works for A [M,512] and W [K,N])
// ---------------------------------------------------------------------------
__global__ __launch_bounds__(256) void conv_kernel(
    const float* __restrict__ src, __nv_bfloat16* __restrict__ hi,
    __nv_bfloat16* __restrict__ lo, size_t total) {
    size_t t = (size_t)blockIdx.x * blockDim.x + threadIdx.x;
    size_t base = t * 8;
    if (base >= total) return;
    float v[8];
    *(float4*)v       = *(const float4*)(src + base);
    *(float4*)(v + 4) = *(const float4*)(src + base + 4);
    union { __nv_bfloat16 h[8]; uint4 u; } hv, lv;
    #pragma unroll
    for (int i = 0; i < 8; i++) {
        hv.h[i] = __float2bfloat16(v[i]);
        lv.h[i] = __float2bfloat16(v[i] - __bfloat162float(hv.h[i]));
    }
    *(uint4*)(hi + base) = hv.u;
    *(uint4*)(lo + base) = lv.u;
}

// ---------------------------------------------------------------------------
// bf16 3-term split GEMM via mma.sync (HMMA).
// C[M,N] = Ahi*Bhi + Ahi*Blo + Alo*Bhi + bias[N], fp32 accumulate.
// CTA tile 128x128, BK=32, 256 threads = 8 warps (4 m x 2 n), warp tile 32x64.
// 3-stage cp.async pipeline; MMAs batched into 3 passes of 16 independent
// accumulators each (kills the accumulator RAW serialization).
// ---------------------------------------------------------------------------
#define ST_ALO 10240
#define ST_BHI 20480
#define ST_BLO 29184
#define STAGE_SZ 37888
#define GSMEM (3 * STAGE_SZ)

__device__ __forceinline__ void ld_stage(
    uint32_t st, const __nv_bfloat16* Ahi, const __nv_bfloat16* Alo,
    const __nv_bfloat16* Bhi, const __nv_bfloat16* Blo,
    int mbase, int nbase, int kt, int N, int tid) {
    #pragma unroll
    for (int i = 0; i < 2; i++) {
        int cid = tid + i * 256;
        int row = cid >> 2, cc = cid & 3;
        uint32_t d = st + row * 80 + cc * 16;
        size_t off = (size_t)(mbase + row) * C_DIM + kt * 32 + cc * 8;
        CP16(d,          Ahi + off);
        CP16(d + ST_ALO, Alo + off);
    }
    #pragma unroll
    for (int i = 0; i < 2; i++) {
        int cid = tid + i * 256;
        int row = cid >> 4, cc = cid & 15;
        uint32_t d = st + ST_BHI + row * 272 + cc * 16;
        size_t off = (size_t)(kt * 32 + row) * N + nbase + cc * 8;
        CP16(d,                     Bhi + off);
        CP16(d + (ST_BLO - ST_BHI), Blo + off);
    }
}

__global__ __launch_bounds__(256, 1) void mma_gemm(
    const __nv_bfloat16* __restrict__ Ahi, const __nv_bfloat16* __restrict__ Alo,
    const __nv_bfloat16* __restrict__ Bhi, const __nv_bfloat16* __restrict__ Blo,
    const float* __restrict__ bias, float* __restrict__ C, int N) {
    extern __shared__ __align__(1024) char smem[];
    const uint32_t sb = su32(smem);
    const int tid = threadIdx.x;
    const int lane = tid & 31, wid = tid >> 5;
    const int warp_m = wid & 3, warp_n = wid >> 2;
    const int mbase = blockIdx.y * 128, nbase = blockIdx.x * 128;
    const int KT = C_DIM / 32;  // 16

    float acc[2][8][4];
    #pragma unroll
    for (int a = 0; a < 2; a++)
        #pragma unroll
        for (int b = 0; b < 8; b++)
            #pragma unroll
            for (int c = 0; c < 4; c++) acc[a][b][c] = 0.f;

    ld_stage(sb,            Ahi, Alo, Bhi, Blo, mbase, nbase, 0, N, tid);
    CP_COMMIT();
    ld_stage(sb + STAGE_SZ, Ahi, Alo, Bhi, Blo, mbase, nbase, 1, N, tid);
    CP_COMMIT();

    int cur = 0, nxt = 2;
    for (int kt = 0; kt < KT; kt++) {
        if (kt + 2 < KT)
            ld_stage(sb + nxt * STAGE_SZ, Ahi, Alo, Bhi, Blo,
                     mbase, nbase, kt + 2, N, tid);
        CP_COMMIT();
        CP_WAIT2();
        __syncthreads();

        const uint32_t st = sb + cur * STAGE_SZ;
        #pragma unroll
        for (int ks = 0; ks < 2; ks++) {
            // A hi fragments + B hi fragments
            uint32_t ah[2][4];
            #pragma unroll
            for (int mi = 0; mi < 2; mi++) {
                uint32_t aaddr = st + (warp_m * 32 + mi * 16 + (lane & 15)) * 80
                               + ks * 32 + ((lane >> 4) << 4);
                LDSM4(ah[mi], aaddr);
            }
            uint32_t bh[4][4];
            #pragma unroll
            for (int nb = 0; nb < 4; nb++) {
                uint32_t baddr = st + ST_BHI + (ks * 16 + (lane & 15)) * 272
                               + warp_n * 128 + nb * 32 + ((lane & 16) ? 16 : 0);
                LDSM4T(bh[nb], baddr);
            }
            // pass 1: Ahi * Bhi  (16 independent accumulators)
            #pragma unroll
            for (int nb = 0; nb < 4; nb++)
                #pragma unroll
                for (int mi = 0; mi < 2; mi++)
                    #pragma unroll
                    for (int s = 0; s < 2; s++)
                        MMA16816(acc[mi][nb * 2 + s], ah[mi],
                                 bh[nb][s * 2], bh[nb][s * 2 + 1]);
            // pass 2: Ahi * Blo
            {
                uint32_t bl[4][4];
                #pragma unroll
                for (int nb = 0; nb < 4; nb++) {
                    uint32_t baddr = st + ST_BLO + (ks * 16 + (lane & 15)) * 272
                                   + warp_n * 128 + nb * 32 + ((lane & 16) ? 16 : 0);
                    LDSM4T(bl[nb], baddr);
                }
                #pragma unroll
                for (int nb = 0; nb < 4; nb++)
                    #pragma unroll
                    for (int mi = 0; mi < 2; mi++)
                        #pragma unroll
                        for (int s = 0; s < 2; s++)
                            MMA16816(acc[mi][nb * 2 + s], ah[mi],
                                     bl[nb][s * 2], bl[nb][s * 2 + 1]);
            }
            // pass 3: Alo * Bhi
            {
                uint32_t al[2][4];
                #pragma unroll
                for (int mi = 0; mi < 2; mi++) {
                    uint32_t aaddr = st + ST_ALO
                                   + (warp_m * 32 + mi * 16 + (lane & 15)) * 80
                                   + ks * 32 + ((lane >> 4) << 4);
                    LDSM4(al[mi], aaddr);
                }
                #pragma unroll
                for (int nb = 0; nb < 4; nb++)
                    #pragma unroll
                    for (int mi = 0; mi < 2; mi++)
                        #pragma unroll
                        for (int s = 0; s < 2; s++)
                            MMA16816(acc[mi][nb * 2 + s], al[mi],
                                     bh[nb][s * 2], bh[nb][s * 2 + 1]);
            }
        }
        __syncthreads();
        cur = (cur == 2) ? 0 : cur + 1;
        nxt = (nxt == 2) ? 0 : nxt + 1;
    }

    // epilogue
    const int r0 = lane >> 2, c0 = (lane & 3) * 2;
    #pragma unroll
    for (int mi = 0; mi < 2; mi++) {
        #pragma unroll
        for (int nt = 0; nt < 8; nt++) {
            int row = mbase + warp_m * 32 + mi * 16 + r0;
            int col = nbase + warp_n * 64 + nt * 8 + c0;
            float b0 = bias[col], b1 = bias[col + 1];
            float2 o0 = make_float2(acc[mi][nt][0] + b0, acc[mi][nt][1] + b1);
            float2 o1 = make_float2(acc[mi][nt][2] + b0, acc[mi][nt][3] + b1);
            *(float2*)(C + (size_t)row * N + col)       = o0;
            *(float2*)(C + (size_t)(row + 8) * N + col) = o1;
        }
    }
}

// ---------------------------------------------------------------------------
// Fused attention: one CTA per (b, h). Reads g_qkv fp32 [M,1536], writes
// attention output directly as row-major hi/lo bf16 (GEMM2's A operand).
// smem stride 34 floats (even -> float2 loads, conflict-free: 17c mod 32 is
// a permutation of lanes).
// ---------------------------------------------------------------------------
__global__ __launch_bounds__(256) void attn_kernel(const float* __restrict__ mask)
{
    const int h = blockIdx.x;   // 0..15
    const int b = blockIdx.y;   // 0..4095

    __shared__ float s_q[N_TOK * 34];
    __shared__ float s_k[N_TOK * 34];
    __shared__ float s_v[N_TOK * 34];
    __shared__ float s_a[N_TOK * N_TOK];

    const int tid = threadIdx.x;
    const float scale = 0.17677669529663687f;  // 32^-0.5

    const size_t base = (size_t)b * N_TOK * QKV_N + h * HD;
    for (int t = tid; t < N_TOK * HD; t += 256) {
        int n = t >> 5, d = t & 31;
        size_t g = base + (size_t)n * QKV_N + d;
        s_q[n * 34 + d] = g_qkv[g] * scale;
        s_k[n * 34 + d] = g_qkv[g + C_DIM];
        s_v[n * 34 + d] = g_qkv[g + 2 * C_DIM];
    }
    __syncthreads();

    const float* bias_h = g_bias + h * (N_TOK * N_TOK);
    const float* mask_w = mask + (size_t)(b & (NW - 1)) * (N_TOK * N_TOK);

    for (int e = tid; e < N_TOK * N_TOK; e += 256) {
        int r = e / N_TOK, c = e % N_TOK;
        const float2* qp = (const float2*)(s_q + r * 34);
        const float2* kp = (const float2*)(s_k + c * 34);
        float s = 0.f;
        #pragma unroll
        for (int kk = 0; kk < HD / 2; kk++) {
            float2 qv = qp[kk], kv = kp[kk];
            s = fmaf(qv.x, kv.x, s);
            s = fmaf(qv.y, kv.y, s);
        }
        s_a[e] = s + bias_h[e] + mask_w[e];
    }
    __syncthreads();

    // softmax, one warp per row
    const int warp = tid >> 5, lane = tid & 31;
    for (int r = warp; r < N_TOK; r += 8) {
        float x1 = s_a[r * N_TOK + lane];
        float x2 = (lane + 32 < N_TOK) ? s_a[r * N_TOK + lane + 32] : -1e30f;
        float m = fmaxf(x1, x2);
        #pragma unroll
        for (int o = 16; o; o >>= 1) m = fmaxf(m, __shfl_xor_sync(0xffffffffu, m, o));
        float e1 = __expf(x1 - m);
        float e2 = (lane + 32 < N_TOK) ? __expf(x2 - m) : 0.f;
        float s = e1 + e2;
        #pragma unroll
        for (int o = 16; o; o >>= 1) s += __shfl_xor_sync(0xffffffffu, s, o);
        float inv = 1.f / s;
        s_a[r * N_TOK + lane] = e1 * inv;
        if (lane + 32 < N_TOK) s_a[r * N_TOK + lane + 32] = e2 * inv;
    }
    __syncthreads();

    // out = attn @ v; write row-major hi/lo bf16 for GEMM2.
    if (tid < N_TOK * 4) {
        const int n = tid >> 2, dg = tid & 3;
        float acc[8];
        #pragma unroll
        for (int j = 0; j < 8; j++) acc[j] = 0.f;
        for (int m = 0; m < N_TOK; m++) {
            float a = s_a[n * N_TOK + m];
            const float2* vp = (const float2*)(s_v + m * 34 + dg * 8);
            #pragma unroll
            for (int j = 0; j < 4; j++) {
                float2 v2 = vp[j];
                acc[j * 2]     = fmaf(a, v2.x, acc[j * 2]);
                acc[j * 2 + 1] = fmaf(a, v2.y, acc[j * 2 + 1]);
            }
        }
        union { __nv_bfloat16 hv[8]; uint4 u; } H, L;
        #pragma unroll
        for (int j = 0; j < 8; j++) {
            H.hv[j] = __float2bfloat16(acc[j]);
            L.hv[j] = __float2bfloat16(acc[j] - __bfloat162float(H.hv[j]));
        }
        const int grow = b * N_TOK + n;          // global M row
        const int kcol = h * HD + dg * 8;        // global K col
        size_t off = (size_t)grow * C_DIM + kcol;
        *(uint4*)(g_a2hi + off) = H.u;
        *(uint4*)(g_a2lo + off) = L.u;
    }
}

// ---------------------------------------------------------------------------
extern "C" void kernel_launch(void* const* d_in, const int* in_sizes, int n_in,
                              void* d_out, int out_size) {
    const float* x      = (const float*)d_in[0];
    const float* mask   = (const float*)d_in[1];
    const float* qkv_w  = (const float*)d_in[2];
    const float* qkv_b  = (const float*)d_in[3];
    const float* proj_w = (const float*)d_in[4];
    const float* proj_b = (const float*)d_in[5];
    const float* table  = (const float*)d_in[6];
    const int*   rpi    = (const int*)d_in[7];
    float* out = (float*)d_out;

    float* qkv_buf;           cudaGetSymbolAddress((void**)&qkv_buf, g_qkv);
    __nv_bfloat16 *a1hi, *a1lo, *a2hi, *a2lo, *b1hi, *b1lo, *b2hi, *b2lo;
    cudaGetSymbolAddress((void**)&a1hi, g_a1hi);
    cudaGetSymbolAddress((void**)&a1lo, g_a1lo);
    cudaGetSymbolAddress((void**)&a2hi, g_a2hi);
    cudaGetSymbolAddress((void**)&a2lo, g_a2lo);
    cudaGetSymbolAddress((void**)&b1hi, g_b1hi);
    cudaGetSymbolAddress((void**)&b1lo, g_b1lo);
    cudaGetSymbolAddress((void**)&b2hi, g_b2hi);
    cudaGetSymbolAddress((void**)&b2lo, g_b2lo);

    cudaFuncSetAttribute(mma_gemm, cudaFuncAttributeMaxDynamicSharedMemorySize,
                         GSMEM);

    // 1. bias table expansion
    {
        int total = H_NUM * N_TOK * N_TOK;
        bias_kernel<<<(total + 255) / 256, 256>>>(table, rpi);
    }
    // 2. conversions
    {
        size_t ta = (size_t)M_ROWS * C_DIM;
        conv_kernel<<<(unsigned)((ta / 8 + 255) / 256), 256>>>(x, a1hi, a1lo, ta);
        size_t tb1 = (size_t)C_DIM * QKV_N;
        conv_kernel<<<(unsigned)((tb1 / 8 + 255) / 256), 256>>>(qkv_w, b1hi, b1lo, tb1);
        size_t tb2 = (size_t)C_DIM * C_DIM;
        conv_kernel<<<(unsigned)((tb2 / 8 + 255) / 256), 256>>>(proj_w, b2hi, b2lo, tb2);
    }
    // 3. QKV GEMM: [200704,512] x [512,1536] + qkv_b -> g_qkv (fp32)
    {
        dim3 grid(QKV_N / 128, M_ROWS / 128);
        mma_gemm<<<grid, 256, GSMEM>>>(a1hi, a1lo, b1hi, b1lo, qkv_b,
                                       qkv_buf, QKV_N);
    }
    // 4. fused window attention -> a2 hi/lo bf16
    {
        dim3 grid(H_NUM, B_WIN);
        attn_kernel<<<grid, 256>>>(mask);
    }
    // 5. proj GEMM: [200704,512] x [512,512] + proj_b -> out
    {
        dim3 grid(C_DIM / 128, M_ROWS / 128);
        mma_gemm<<<grid, 256, GSMEM>>>(a2hi, a2lo, b2hi, b2lo, proj_b,
                                       out, C_DIM);
    }
}